// round 1
// baseline (speedup 1.0000x reference)
#include <cuda_runtime.h>
#include <math.h>

// ---- static problem dims ----
#define BN      64      // batch (nodes)
#define NCL     128
#define NC      512     // total channels
#define REP     2048    // rep components
#define DD      512     // folded dim
#define NORM_EPS 1e-2f
#define BN_EPS   1e-5f

__device__ __constant__ int REP_OFF_C[4] = {0, 128, 512, 1152};

// ---- scratch (__device__ globals: allocation-free) ----
__device__ float g_s[BN * REP];      // gauge tensor
__device__ float norm_s[BN * NC];    // per-(l,channel) norms
__device__ float nbn_s[BN * NC];     // batchnormed norms
__device__ float h_s[BN * NC];       // MLP hidden
__device__ float n1_s[BN * NC];      // MLP out
__device__ float a2p_s[BN * 8 * 4];  // partial bilinear sums (8 chunks per n)
__device__ float M_s[BN * 16];       // per-n gated 4x4: M[d][c] = gate[n,d]*Wt[d,c]

// ============================================================
// K1: per-node norms + gauge tensor.  One block per n.
// ============================================================
__global__ void k_norm_gauge(const float* __restrict__ x1d) {
    int n = blockIdx.x;
    __shared__ float xs[REP];   // 8 KB
    __shared__ float ns[NC];    // 2 KB
    const float* xr = x1d + n * REP;
    for (int i = threadIdx.x; i < REP; i += 256) xs[i] = xr[i];
    __syncthreads();
    for (int c = threadIdx.x; c < NC; c += 256) {
        int l = c >> 7, j = c & 127, off = REP_OFF_C[l], nm = 2 * l + 1;
        float s = 0.f;
        #pragma unroll 7
        for (int m = 0; m < nm; m++) { float v = xs[off + m * 128 + j]; s += v * v; }
        float nv = sqrtf(s);
        ns[c] = nv;
        norm_s[n * NC + c] = nv;
    }
    __syncthreads();
    for (int r = threadIdx.x; r < REP; r += 256) {
        int l = (r < 128) ? 0 : (r < 512) ? 1 : (r < 1152) ? 2 : 3;
        int c = l * 128 + ((r - REP_OFF_C[l]) & 127);
        g_s[n * REP + r] = xs[r] / (ns[c] + NORM_EPS);
    }
}

// ============================================================
// K2: batchnorm over the batch axis (train stats, gamma=1, beta=0).
// One block, 512 threads (one per channel). Coalesced across c.
// ============================================================
__global__ void k_bn() {
    int c = threadIdx.x;
    float mu = 0.f;
    #pragma unroll 8
    for (int n = 0; n < BN; n++) mu += norm_s[n * NC + c];
    mu *= (1.f / BN);
    float var = 0.f;
    #pragma unroll 8
    for (int n = 0; n < BN; n++) { float d = norm_s[n * NC + c] - mu; var += d * d; }
    var *= (1.f / BN);
    float inv = 1.f / sqrtf(var + BN_EPS);
    #pragma unroll 8
    for (int n = 0; n < BN; n++) nbn_s[n * NC + c] = (norm_s[n * NC + c] - mu) * inv;
}

// ============================================================
// K3/K4: [64,512] @ W^T (W row-major [o,k]) + bias, optional swish.
// grid (4 o-tiles, 8 n-groups), 128 threads. W staged in smem in k-chunks
// of 32 with a [32][129] layout (conflict-free transpose-in-smem).
// which=0: nbn_s -> h_s with swish;  which=1: h_s -> n1_s, linear.
// ============================================================
__global__ void k_gemm(const float* __restrict__ W, const float* __restrict__ bias, int which) {
    const float* X = which ? h_s : nbn_s;
    float* Y       = which ? n1_s : h_s;
    __shared__ float xs[8][512];    // 16 KB
    __shared__ float ws[32][129];   // 16.5 KB
    int otile = blockIdx.x * 128;
    int ng    = blockIdx.y * 8;
    int tid   = threadIdx.x;
    for (int i = tid; i < 8 * 512; i += 128) {
        int j = i >> 9, k = i & 511;
        xs[j][k] = X[(ng + j) * NC + k];
    }
    float acc[8] = {0.f, 0.f, 0.f, 0.f, 0.f, 0.f, 0.f, 0.f};
    for (int kc = 0; kc < 16; kc++) {
        __syncthreads();
        for (int i = tid; i < 128 * 32; i += 128) {
            int kk = i & 31, orow = i >> 5;
            ws[kk][orow] = W[(otile + orow) * NC + kc * 32 + kk];
        }
        __syncthreads();
        #pragma unroll
        for (int kk = 0; kk < 32; kk++) {
            float wv = ws[kk][tid];
            #pragma unroll
            for (int j = 0; j < 8; j++)
                acc[j] = fmaf(xs[j][kc * 32 + kk], wv, acc[j]);
        }
    }
    int o = otile + tid;
    float b = bias[o];
    for (int j = 0; j < 8; j++) {
        float v = acc[j] + b;
        if (!which) v = v / (1.f + expf(-v));   // swish
        Y[(ng + j) * NC + o] = v;
    }
}

// ============================================================
// K5: IELin (per-degree channel mixing) fused with scalar_mul.
// Writes x1d_new directly into d_out. 128 blocks of 8 (n,m)-rows,
// 128 threads (one per output channel). Each block is within one l
// (row-count boundaries 64/256/576 are all multiples of 8).
// ============================================================
__global__ void k_ielin(const float* __restrict__ Wie, float* __restrict__ x1dout) {
    __shared__ float gs[8][128];   // 4 KB
    __shared__ float ws[32][129];  // 16.5 KB
    __shared__ int nrow[8], mrow[8];
    int rowbase = blockIdx.x * 8;
    int l, lbase;
    if (rowbase < 64)       { l = 0; lbase = 0; }
    else if (rowbase < 256) { l = 1; lbase = 64; }
    else if (rowbase < 576) { l = 2; lbase = 256; }
    else                    { l = 3; lbase = 576; }
    int nm = 2 * l + 1, off = REP_OFF_C[l];
    int tid = threadIdx.x;
    if (tid < 8) {
        int rr = rowbase + tid - lbase;
        nrow[tid] = rr / nm;
        mrow[tid] = rr - nrow[tid] * nm;
    }
    __syncthreads();
    #pragma unroll
    for (int j = 0; j < 8; j++)
        gs[j][tid] = g_s[nrow[j] * REP + off + mrow[j] * 128 + tid];
    float acc[8] = {0.f, 0.f, 0.f, 0.f, 0.f, 0.f, 0.f, 0.f};
    for (int ic = 0; ic < 4; ic++) {
        __syncthreads();
        for (int i = tid; i < 128 * 32; i += 128) {
            int ii = i & 31, orow = i >> 5;
            ws[ii][orow] = Wie[(l * 128 + orow) * 128 + ic * 32 + ii];
        }
        __syncthreads();
        #pragma unroll
        for (int ii = 0; ii < 32; ii++) {
            float wv = ws[ii][tid];
            #pragma unroll
            for (int j = 0; j < 8; j++)
                acc[j] = fmaf(gs[j][ic * 32 + ii], wv, acc[j]);
        }
    }
    for (int j = 0; j < 8; j++) {
        int n = nrow[j];
        x1dout[n * REP + off + mrow[j] * 128 + tid] = acc[j] * n1_s[n * NC + l * 128 + tid];
    }
}

// ============================================================
// K6: bilinear reduction  a2[n,c] = sum_{p,q} f[p,c]*x2d[n,p,q,c]*f[q,c]
// f = x1d_new viewed as [n][512] float4. grid (8 chunks, 64 n), 256 thr.
// Each block streams 64 rows (512 KB) with coalesced float4 loads;
// deterministic per-chunk partial sums (no atomics).
// ============================================================
__global__ void k_reduce(const float* __restrict__ x2d, const float* __restrict__ x1dnew) {
    int n = blockIdx.y, chunk = blockIdx.x;
    __shared__ float4 fs[512];      // 8 KB
    __shared__ float  wacc[8][4];
    int tid = threadIdx.x;
    const float4* f4 = (const float4*)x1dnew + n * 512;
    for (int q = tid; q < 512; q += 256) fs[q] = f4[q];
    __syncthreads();
    int warp = tid >> 5, lane = tid & 31;
    float ax = 0.f, ay = 0.f, az = 0.f, aw = 0.f;
    for (int r = 0; r < 8; r++) {
        int p = chunk * 64 + warp * 8 + r;
        float4 fp = fs[p];
        const float4* row = (const float4*)x2d + ((size_t)n * 512 + p) * 512;
        #pragma unroll 4
        for (int j = 0; j < 16; j++) {
            int q = lane + (j << 5);
            float4 v  = row[q];
            float4 fq = fs[q];
            ax = fmaf(v.x * fq.x, fp.x, ax);
            ay = fmaf(v.y * fq.y, fp.y, ay);
            az = fmaf(v.z * fq.z, fp.z, az);
            aw = fmaf(v.w * fq.w, fp.w, aw);
        }
    }
    #pragma unroll
    for (int s = 16; s > 0; s >>= 1) {
        ax += __shfl_xor_sync(0xffffffff, ax, s);
        ay += __shfl_xor_sync(0xffffffff, ay, s);
        az += __shfl_xor_sync(0xffffffff, az, s);
        aw += __shfl_xor_sync(0xffffffff, aw, s);
    }
    if (lane == 0) { wacc[warp][0] = ax; wacc[warp][1] = ay; wacc[warp][2] = az; wacc[warp][3] = aw; }
    __syncthreads();
    if (tid < 4) {
        float s = 0.f;
        #pragma unroll
        for (int w = 0; w < 8; w++) s += wacc[w][tid];
        a2p_s[(n * 8 + chunk) * 4 + tid] = s;
    }
}

// ============================================================
// K7: gate = swish(a2 @ Wg^T + bg); fold gate into per-n 4x4:
//     M[n][d][c] = gate[n,d] * Wt[d,c]. One block, 64 threads.
// ============================================================
__global__ void k_gate(const float* __restrict__ Wg, const float* __restrict__ bg,
                       const float* __restrict__ Wt) {
    int n = threadIdx.x;
    if (n >= BN) return;
    float a2[4] = {0.f, 0.f, 0.f, 0.f};
    #pragma unroll
    for (int ch = 0; ch < 8; ch++)
        #pragma unroll
        for (int c = 0; c < 4; c++)
            a2[c] += a2p_s[(n * 8 + ch) * 4 + c];
    #pragma unroll
    for (int d = 0; d < 4; d++) {
        float pre = bg[d];
        #pragma unroll
        for (int c = 0; c < 4; c++) pre = fmaf(a2[c], Wg[d * 4 + c], pre);
        float gate = pre / (1.f + expf(-pre));
        #pragma unroll
        for (int c = 0; c < 4; c++) M_s[n * 16 + d * 4 + c] = gate * Wt[d * 4 + c];
    }
}

// ============================================================
// K8: x2d_new[n,p,q,:] = M[n] * x2d[n,p,q,:]  (4x4 matvec per float4)
// grid (64 blocks per n, 64 n), 256 threads, 16 float4 per thread.
// Pure stream: 256 MB read + 256 MB write.
// ============================================================
__global__ void k_pass2(const float* __restrict__ x2d, float* __restrict__ x2dout) {
    int n = blockIdx.y;
    int tid = threadIdx.x;
    float m[16];
    #pragma unroll
    for (int i = 0; i < 16; i++) m[i] = M_s[n * 16 + i];
    const float4* in4  = (const float4*)x2d    + (size_t)n * 262144;
    float4*       out4 = (float4*)      x2dout + (size_t)n * 262144;
    int base = blockIdx.x * 4096 + tid;
    #pragma unroll 4
    for (int j = 0; j < 16; j++) {
        int idx = base + j * 256;
        float4 v = in4[idx];
        float4 o;
        o.x = m[0]  * v.x + m[1]  * v.y + m[2]  * v.z + m[3]  * v.w;
        o.y = m[4]  * v.x + m[5]  * v.y + m[6]  * v.z + m[7]  * v.w;
        o.z = m[8]  * v.x + m[9]  * v.y + m[10] * v.z + m[11] * v.w;
        o.w = m[12] * v.x + m[13] * v.y + m[14] * v.z + m[15] * v.w;
        out4[idx] = o;
    }
}

// ============================================================
extern "C" void kernel_launch(void* const* d_in, const int* in_sizes, int n_in,
                              void* d_out, int out_size) {
    const float* x1d = (const float*)d_in[0];
    const float* x2d = (const float*)d_in[1];
    const float* W1  = (const float*)d_in[2];
    const float* b1  = (const float*)d_in[3];
    const float* W2  = (const float*)d_in[4];
    const float* b2  = (const float*)d_in[5];
    const float* Wie = (const float*)d_in[6];
    const float* Wt  = (const float*)d_in[7];
    const float* Wg  = (const float*)d_in[8];
    const float* bg  = (const float*)d_in[9];
    float* out = (float*)d_out;
    float* x1dnew = out;                       // [64, 2048]
    float* x2dnew = out + (size_t)BN * REP;    // [64, 512, 512, 4]

    k_norm_gauge<<<BN, 256>>>(x1d);
    k_bn<<<1, 512>>>();
    k_gemm<<<dim3(4, 8), 128>>>(W1, b1, 0);    // swish
    k_gemm<<<dim3(4, 8), 128>>>(W2, b2, 1);    // linear
    k_ielin<<<128, 128>>>(Wie, x1dnew);
    k_reduce<<<dim3(8, BN), 256>>>(x2d, x1dnew);
    k_gate<<<1, 64>>>(Wg, bg, Wt);
    k_pass2<<<dim3(64, BN), 256>>>(x2d, x2dnew);
}

// round 2
// speedup vs baseline: 1.0388x; 1.0388x over previous
#include <cuda_runtime.h>
#include <math.h>

// ---- static problem dims ----
#define BN      64      // batch (nodes)
#define NCL     128
#define NC      512     // total channels
#define REP     2048    // rep components
#define DD      512     // folded dim
#define NORM_EPS 1e-2f
#define BN_EPS   1e-5f

__device__ __constant__ int REP_OFF_C[4] = {0, 128, 512, 1152};

// ---- scratch (__device__ globals: allocation-free) ----
__device__ float g_s[BN * REP];      // gauge tensor
__device__ float norm_s[BN * NC];    // per-(l,channel) norms
__device__ float nbn_s[BN * NC];     // batchnormed norms
__device__ float h_s[BN * NC];       // MLP hidden
__device__ float n1_s[BN * NC];      // MLP out
__device__ float a2p_s[BN * 8 * 4];  // partial bilinear sums (8 chunks per n)
__device__ float M_s[BN * 16];       // per-n gated 4x4: M[d][c] = gate[n,d]*Wt[d,c]

// ============================================================
// K1: per-node norms + gauge tensor.  One block per n.
// ============================================================
__global__ void k_norm_gauge(const float* __restrict__ x1d) {
    int n = blockIdx.x;
    __shared__ float xs[REP];   // 8 KB
    __shared__ float ns[NC];    // 2 KB
    const float* xr = x1d + n * REP;
    for (int i = threadIdx.x; i < REP; i += 256) xs[i] = xr[i];
    __syncthreads();
    for (int c = threadIdx.x; c < NC; c += 256) {
        int l = c >> 7, j = c & 127, off = REP_OFF_C[l], nm = 2 * l + 1;
        float s = 0.f;
        #pragma unroll 7
        for (int m = 0; m < nm; m++) { float v = xs[off + m * 128 + j]; s += v * v; }
        float nv = sqrtf(s);
        ns[c] = nv;
        norm_s[n * NC + c] = nv;
    }
    __syncthreads();
    for (int r = threadIdx.x; r < REP; r += 256) {
        int l = (r < 128) ? 0 : (r < 512) ? 1 : (r < 1152) ? 2 : 3;
        int c = l * 128 + ((r - REP_OFF_C[l]) & 127);
        g_s[n * REP + r] = xs[r] / (ns[c] + NORM_EPS);
    }
}

// ============================================================
// K2: batchnorm over batch axis. grid 4 x 128 threads, one channel/thread.
// ============================================================
__global__ void k_bn() {
    int c = blockIdx.x * 128 + threadIdx.x;
    float mu = 0.f;
    #pragma unroll 8
    for (int n = 0; n < BN; n++) mu += norm_s[n * NC + c];
    mu *= (1.f / BN);
    float var = 0.f;
    #pragma unroll 8
    for (int n = 0; n < BN; n++) { float d = norm_s[n * NC + c] - mu; var += d * d; }
    var *= (1.f / BN);
    float inv = 1.f / sqrtf(var + BN_EPS);
    #pragma unroll 8
    for (int n = 0; n < BN; n++) nbn_s[n * NC + c] = (norm_s[n * NC + c] - mu) * inv;
}

// ============================================================
// K3/K4: [64,512] @ W^T + bias, optional swish.
// grid (4 o-tiles of 128, 16 n-groups of 4), 128 threads (tid = o in tile).
// xs staged TRANSPOSED ([k][j], float4-readable broadcast); each thread
// computes 4 n-outputs so per-k LDS cost is 1 ws read + 1 LDS.128 bcast.
// ============================================================
__global__ void k_gemm(const float* __restrict__ W, const float* __restrict__ bias, int which) {
    const float* X = which ? h_s : nbn_s;
    float* Y       = which ? n1_s : h_s;
    __shared__ float xs[512][4];    // 8 KB, transposed [k][j]
    __shared__ float ws[32][129];   // 16.5 KB
    int otile = blockIdx.x * 128;
    int ng    = blockIdx.y * 4;
    int tid   = threadIdx.x;
    for (int i = tid; i < 4 * 512; i += 128) {
        int j = i >> 9, k = i & 511;
        xs[k][j] = X[(ng + j) * NC + k];
    }
    float acc0 = 0.f, acc1 = 0.f, acc2 = 0.f, acc3 = 0.f;
    for (int kc = 0; kc < 16; kc++) {
        __syncthreads();
        for (int i = tid; i < 128 * 32; i += 128) {
            int kk = i & 31, orow = i >> 5;
            ws[kk][orow] = W[(otile + orow) * NC + kc * 32 + kk];
        }
        __syncthreads();
        #pragma unroll
        for (int kk = 0; kk < 32; kk++) {
            float wv = ws[kk][tid];
            float4 xv = *(const float4*)&xs[kc * 32 + kk][0];
            acc0 = fmaf(xv.x, wv, acc0);
            acc1 = fmaf(xv.y, wv, acc1);
            acc2 = fmaf(xv.z, wv, acc2);
            acc3 = fmaf(xv.w, wv, acc3);
        }
    }
    int o = otile + tid;
    float b = bias[o];
    float v[4] = {acc0 + b, acc1 + b, acc2 + b, acc3 + b};
    #pragma unroll
    for (int j = 0; j < 4; j++) {
        float u = v[j];
        if (!which) u = u / (1.f + expf(-u));   // swish
        Y[(ng + j) * NC + o] = u;
    }
}

// ============================================================
// K5: IELin fused with scalar_mul -> x1d_new (into d_out).
// 256 blocks x 512 threads: 4 (n,m)-rows per block (all within one l:
// row boundaries 64/256/576 are multiples of 4), 1 output per thread.
// ============================================================
__global__ void k_ielin(const float* __restrict__ Wie, float* __restrict__ x1dout) {
    __shared__ float gsT[128][5];   // transposed [i][j]
    __shared__ float ws[32][129];
    int rowbase = blockIdx.x * 4;
    int l, lbase;
    if (rowbase < 64)       { l = 0; lbase = 0; }
    else if (rowbase < 256) { l = 1; lbase = 64; }
    else if (rowbase < 576) { l = 2; lbase = 256; }
    else                    { l = 3; lbase = 576; }
    int nm = 2 * l + 1, off = REP_OFF_C[l];
    int tid = threadIdx.x;
    int j = tid >> 7, o = tid & 127;
    int rr = rowbase + j - lbase;
    int n = rr / nm, m = rr - n * nm;
    gsT[o][j] = g_s[n * REP + off + m * 128 + o];
    float acc = 0.f;
    for (int ic = 0; ic < 4; ic++) {
        __syncthreads();
        for (int i = tid; i < 128 * 32; i += 512) {
            int ii = i & 31, orow = i >> 5;
            ws[ii][orow] = Wie[(l * 128 + orow) * 128 + ic * 32 + ii];
        }
        __syncthreads();
        #pragma unroll
        for (int ii = 0; ii < 32; ii++)
            acc = fmaf(gsT[ic * 32 + ii][j], ws[ii][o], acc);
    }
    x1dout[n * REP + off + m * 128 + o] = acc * n1_s[n * NC + l * 128 + o];
}

// ============================================================
// K6: bilinear reduction  a2[n,c] = sum_{p,q} f[p,c]*x2d[n,p,q,c]*f[q,c]
// grid (8 chunks, 64 n), 256 threads. Deterministic per-chunk partials.
// ============================================================
__global__ void k_reduce(const float* __restrict__ x2d, const float* __restrict__ x1dnew) {
    int n = blockIdx.y, chunk = blockIdx.x;
    __shared__ float4 fs[512];      // 8 KB
    __shared__ float  wacc[8][4];
    int tid = threadIdx.x;
    const float4* f4 = (const float4*)x1dnew + n * 512;
    for (int q = tid; q < 512; q += 256) fs[q] = f4[q];
    __syncthreads();
    int warp = tid >> 5, lane = tid & 31;
    float ax = 0.f, ay = 0.f, az = 0.f, aw = 0.f;
    for (int r = 0; r < 8; r++) {
        int p = chunk * 64 + warp * 8 + r;
        float4 fp = fs[p];
        const float4* row = (const float4*)x2d + ((size_t)n * 512 + p) * 512;
        #pragma unroll
        for (int j = 0; j < 16; j++) {
            int q = lane + (j << 5);
            float4 v  = row[q];
            float4 fq = fs[q];
            ax = fmaf(v.x * fq.x, fp.x, ax);
            ay = fmaf(v.y * fq.y, fp.y, ay);
            az = fmaf(v.z * fq.z, fp.z, az);
            aw = fmaf(v.w * fq.w, fp.w, aw);
        }
    }
    #pragma unroll
    for (int s = 16; s > 0; s >>= 1) {
        ax += __shfl_xor_sync(0xffffffff, ax, s);
        ay += __shfl_xor_sync(0xffffffff, ay, s);
        az += __shfl_xor_sync(0xffffffff, az, s);
        aw += __shfl_xor_sync(0xffffffff, aw, s);
    }
    if (lane == 0) { wacc[warp][0] = ax; wacc[warp][1] = ay; wacc[warp][2] = az; wacc[warp][3] = aw; }
    __syncthreads();
    if (tid < 4) {
        float s = 0.f;
        #pragma unroll
        for (int w = 0; w < 8; w++) s += wacc[w][tid];
        a2p_s[(n * 8 + chunk) * 4 + tid] = s;
    }
}

// ============================================================
// K7: gate = swish(a2 @ Wg^T + bg); fold into per-n 4x4 M.
// ============================================================
__global__ void k_gate(const float* __restrict__ Wg, const float* __restrict__ bg,
                       const float* __restrict__ Wt) {
    int n = threadIdx.x;
    if (n >= BN) return;
    float a2[4] = {0.f, 0.f, 0.f, 0.f};
    #pragma unroll
    for (int ch = 0; ch < 8; ch++)
        #pragma unroll
        for (int c = 0; c < 4; c++)
            a2[c] += a2p_s[(n * 8 + ch) * 4 + c];
    #pragma unroll
    for (int d = 0; d < 4; d++) {
        float pre = bg[d];
        #pragma unroll
        for (int c = 0; c < 4; c++) pre = fmaf(a2[c], Wg[d * 4 + c], pre);
        float gate = pre / (1.f + expf(-pre));
        #pragma unroll
        for (int c = 0; c < 4; c++) M_s[n * 16 + d * 4 + c] = gate * Wt[d * 4 + c];
    }
}

// ============================================================
// K8: x2d_new[n,p,q,:] = M[n] * x2d[n,p,q,:]  (pure stream, 512 MB r+w)
// ============================================================
__global__ void k_pass2(const float* __restrict__ x2d, float* __restrict__ x2dout) {
    int n = blockIdx.y;
    int tid = threadIdx.x;
    float m[16];
    #pragma unroll
    for (int i = 0; i < 16; i++) m[i] = M_s[n * 16 + i];
    const float4* in4  = (const float4*)x2d    + (size_t)n * 262144;
    float4*       out4 = (float4*)      x2dout + (size_t)n * 262144;
    int base = blockIdx.x * 4096 + tid;
    #pragma unroll 8
    for (int j = 0; j < 16; j++) {
        int idx = base + j * 256;
        float4 v = in4[idx];
        float4 o;
        o.x = m[0]  * v.x + m[1]  * v.y + m[2]  * v.z + m[3]  * v.w;
        o.y = m[4]  * v.x + m[5]  * v.y + m[6]  * v.z + m[7]  * v.w;
        o.z = m[8]  * v.x + m[9]  * v.y + m[10] * v.z + m[11] * v.w;
        o.w = m[12] * v.x + m[13] * v.y + m[14] * v.z + m[15] * v.w;
        out4[idx] = o;
    }
}

// ============================================================
extern "C" void kernel_launch(void* const* d_in, const int* in_sizes, int n_in,
                              void* d_out, int out_size) {
    const float* x1d = (const float*)d_in[0];
    const float* x2d = (const float*)d_in[1];
    const float* W1  = (const float*)d_in[2];
    const float* b1  = (const float*)d_in[3];
    const float* W2  = (const float*)d_in[4];
    const float* b2  = (const float*)d_in[5];
    const float* Wie = (const float*)d_in[6];
    const float* Wt  = (const float*)d_in[7];
    const float* Wg  = (const float*)d_in[8];
    const float* bg  = (const float*)d_in[9];
    float* out = (float*)d_out;
    float* x1dnew = out;                       // [64, 2048]
    float* x2dnew = out + (size_t)BN * REP;    // [64, 512, 512, 4]

    k_norm_gauge<<<BN, 256>>>(x1d);
    k_bn<<<4, 128>>>();
    k_gemm<<<dim3(4, 16), 128>>>(W1, b1, 0);   // swish
    k_gemm<<<dim3(4, 16), 128>>>(W2, b2, 1);   // linear
    k_ielin<<<256, 512>>>(Wie, x1dnew);
    k_reduce<<<dim3(8, BN), 256>>>(x2d, x1dnew);
    k_gate<<<1, 64>>>(Wg, bg, Wt);
    k_pass2<<<dim3(64, BN), 256>>>(x2d, x2dnew);
}

// round 3
// speedup vs baseline: 1.7319x; 1.6672x over previous
#include <cuda_runtime.h>
#include <math.h>

// ---- static problem dims ----
#define BN      64      // batch (nodes)
#define NCL     128
#define NC      512     // total channels
#define REP     2048    // rep components
#define DD      512     // folded dim
#define NORM_EPS 1e-2f
#define BN_EPS   1e-5f

__device__ __constant__ int REP_OFF_C[4] = {0, 128, 512, 1152};

// ---- scratch (__device__ globals: allocation-free) ----
__device__ float g_s[BN * REP];      // gauge tensor
__device__ float norm_s[BN * NC];    // per-(l,channel) norms
__device__ float nbn_s[BN * NC];     // batchnormed norms
__device__ float h_s[BN * NC];       // MLP hidden
__device__ float n1_s[BN * NC];      // MLP out
__device__ float a2p_s[BN * 8 * 4];  // partial bilinear sums (8 chunks per n)
__device__ float M_s[BN * 16];       // per-n gated 4x4: M[d][c] = gate[n,d]*Wt[d,c]

// ============================================================
// K1: per-node norms + gauge tensor.  One block per n.
// ============================================================
__global__ void k_norm_gauge(const float* __restrict__ x1d) {
    int n = blockIdx.x;
    __shared__ float xs[REP];   // 8 KB
    __shared__ float ns[NC];    // 2 KB
    const float* xr = x1d + n * REP;
    for (int i = threadIdx.x; i < REP; i += 256) xs[i] = xr[i];
    __syncthreads();
    for (int c = threadIdx.x; c < NC; c += 256) {
        int l = c >> 7, j = c & 127, off = REP_OFF_C[l], nm = 2 * l + 1;
        float s = 0.f;
        #pragma unroll 7
        for (int m = 0; m < nm; m++) { float v = xs[off + m * 128 + j]; s += v * v; }
        float nv = sqrtf(s);
        ns[c] = nv;
        norm_s[n * NC + c] = nv;
    }
    __syncthreads();
    for (int r = threadIdx.x; r < REP; r += 256) {
        int l = (r < 128) ? 0 : (r < 512) ? 1 : (r < 1152) ? 2 : 3;
        int c = l * 128 + ((r - REP_OFF_C[l]) & 127);
        g_s[n * REP + r] = xs[r] / (ns[c] + NORM_EPS);
    }
}

// ============================================================
// K2: batchnorm over batch axis. grid 4 x 128 threads, one channel/thread.
// ============================================================
__global__ void k_bn() {
    int c = blockIdx.x * 128 + threadIdx.x;
    float mu = 0.f;
    #pragma unroll 8
    for (int n = 0; n < BN; n++) mu += norm_s[n * NC + c];
    mu *= (1.f / BN);
    float var = 0.f;
    #pragma unroll 8
    for (int n = 0; n < BN; n++) { float d = norm_s[n * NC + c] - mu; var += d * d; }
    var *= (1.f / BN);
    float inv = 1.f / sqrtf(var + BN_EPS);
    #pragma unroll 8
    for (int n = 0; n < BN; n++) nbn_s[n * NC + c] = (norm_s[n * NC + c] - mu) * inv;
}

// ============================================================
// K3/K4: [64,512] @ W^T + bias, optional swish.
// Warp-per-output-channel, lanes stride k, W loaded DIRECTLY from gmem
// with 16 independent coalesced LDGs (deep MLP, no staged-smem latency
// chain). grid (64 o-groups of 8, 8 n-groups of 8), 256 threads.
// ============================================================
__global__ void k_gemm(const float* __restrict__ W, const float* __restrict__ bias, int which) {
    const float* X = which ? h_s : nbn_s;
    float* Y       = which ? n1_s : h_s;
    __shared__ float xs[8][512];    // 16 KB
    int ng  = blockIdx.y * 8;
    int tid = threadIdx.x, warp = tid >> 5, lane = tid & 31;
    int o = blockIdx.x * 8 + warp;
    for (int i = tid; i < 8 * 512; i += 256)
        xs[i >> 9][i & 511] = X[(ng + (i >> 9)) * NC + (i & 511)];
    __syncthreads();
    const float* wrow = W + o * NC;
    float a0=0.f,a1=0.f,a2=0.f,a3=0.f,a4=0.f,a5=0.f,a6=0.f,a7=0.f;
    #pragma unroll
    for (int j = 0; j < 16; j++) {
        int k = lane + (j << 5);
        float w = wrow[k];
        a0 = fmaf(w, xs[0][k], a0);
        a1 = fmaf(w, xs[1][k], a1);
        a2 = fmaf(w, xs[2][k], a2);
        a3 = fmaf(w, xs[3][k], a3);
        a4 = fmaf(w, xs[4][k], a4);
        a5 = fmaf(w, xs[5][k], a5);
        a6 = fmaf(w, xs[6][k], a6);
        a7 = fmaf(w, xs[7][k], a7);
    }
    #pragma unroll
    for (int s = 16; s > 0; s >>= 1) {
        a0 += __shfl_xor_sync(0xffffffff, a0, s);
        a1 += __shfl_xor_sync(0xffffffff, a1, s);
        a2 += __shfl_xor_sync(0xffffffff, a2, s);
        a3 += __shfl_xor_sync(0xffffffff, a3, s);
        a4 += __shfl_xor_sync(0xffffffff, a4, s);
        a5 += __shfl_xor_sync(0xffffffff, a5, s);
        a6 += __shfl_xor_sync(0xffffffff, a6, s);
        a7 += __shfl_xor_sync(0xffffffff, a7, s);
    }
    if (lane == 0) {
        float b = bias[o];
        float v[8] = {a0+b, a1+b, a2+b, a3+b, a4+b, a5+b, a6+b, a7+b};
        #pragma unroll
        for (int j = 0; j < 8; j++) {
            float u = v[j];
            if (!which) u = u / (1.f + expf(-u));   // swish
            Y[(ng + j) * NC + o] = u;
        }
    }
}

// ============================================================
// K5: IELin fused with scalar_mul -> x1d_new (into d_out).
// Warp-per-output-channel over 8 (n,m)-rows; Wie row loaded directly
// (4 independent LDGs). grid (128 rowgroups of 8, 16 o-groups of 8),
// 256 threads. Row boundaries 64/256/576 are multiples of 8.
// ============================================================
__global__ void k_ielin(const float* __restrict__ Wie, float* __restrict__ x1dout) {
    __shared__ float gs[8][128];   // 4 KB
    __shared__ int nrow[8], mrow[8];
    int rowbase = blockIdx.x * 8;
    int l, lbase;
    if (rowbase < 64)       { l = 0; lbase = 0; }
    else if (rowbase < 256) { l = 1; lbase = 64; }
    else if (rowbase < 576) { l = 2; lbase = 256; }
    else                    { l = 3; lbase = 576; }
    int nm = 2 * l + 1, off = REP_OFF_C[l];
    int tid = threadIdx.x, warp = tid >> 5, lane = tid & 31;
    if (tid < 8) {
        int rr = rowbase + tid - lbase;
        nrow[tid] = rr / nm;
        mrow[tid] = rr - nrow[tid] * nm;
    }
    __syncthreads();
    for (int idx = tid; idx < 8 * 128; idx += 256) {
        int j = idx >> 7, i = idx & 127;
        gs[j][i] = g_s[nrow[j] * REP + off + mrow[j] * 128 + i];
    }
    __syncthreads();
    int o = blockIdx.y * 8 + warp;
    const float* wrow = Wie + (l * 128 + o) * 128;
    float a0=0.f,a1=0.f,a2=0.f,a3=0.f,a4=0.f,a5=0.f,a6=0.f,a7=0.f;
    #pragma unroll
    for (int j = 0; j < 4; j++) {
        int k = lane + (j << 5);
        float w = wrow[k];
        a0 = fmaf(w, gs[0][k], a0);
        a1 = fmaf(w, gs[1][k], a1);
        a2 = fmaf(w, gs[2][k], a2);
        a3 = fmaf(w, gs[3][k], a3);
        a4 = fmaf(w, gs[4][k], a4);
        a5 = fmaf(w, gs[5][k], a5);
        a6 = fmaf(w, gs[6][k], a6);
        a7 = fmaf(w, gs[7][k], a7);
    }
    #pragma unroll
    for (int s = 16; s > 0; s >>= 1) {
        a0 += __shfl_xor_sync(0xffffffff, a0, s);
        a1 += __shfl_xor_sync(0xffffffff, a1, s);
        a2 += __shfl_xor_sync(0xffffffff, a2, s);
        a3 += __shfl_xor_sync(0xffffffff, a3, s);
        a4 += __shfl_xor_sync(0xffffffff, a4, s);
        a5 += __shfl_xor_sync(0xffffffff, a5, s);
        a6 += __shfl_xor_sync(0xffffffff, a6, s);
        a7 += __shfl_xor_sync(0xffffffff, a7, s);
    }
    if (lane == 0) {
        float acc[8] = {a0, a1, a2, a3, a4, a5, a6, a7};
        #pragma unroll
        for (int j = 0; j < 8; j++) {
            int n = nrow[j];
            x1dout[n * REP + off + mrow[j] * 128 + o] =
                acc[j] * n1_s[n * NC + l * 128 + o];
        }
    }
}

// ============================================================
// K6: bilinear reduction  a2[n,c] = sum_{p,q} f[p,c]*x2d[n,p,q,c]*f[q,c]
// grid (8 chunks, 64 n), 256 threads. Deterministic per-chunk partials.
// ============================================================
__global__ void k_reduce(const float* __restrict__ x2d, const float* __restrict__ x1dnew) {
    int n = blockIdx.y, chunk = blockIdx.x;
    __shared__ float4 fs[512];      // 8 KB
    __shared__ float  wacc[8][4];
    int tid = threadIdx.x;
    const float4* f4 = (const float4*)x1dnew + n * 512;
    for (int q = tid; q < 512; q += 256) fs[q] = f4[q];
    __syncthreads();
    int warp = tid >> 5, lane = tid & 31;
    float ax = 0.f, ay = 0.f, az = 0.f, aw = 0.f;
    for (int r = 0; r < 8; r++) {
        int p = chunk * 64 + warp * 8 + r;
        float4 fp = fs[p];
        const float4* row = (const float4*)x2d + ((size_t)n * 512 + p) * 512;
        #pragma unroll
        for (int j = 0; j < 16; j++) {
            int q = lane + (j << 5);
            float4 v  = row[q];
            float4 fq = fs[q];
            ax = fmaf(v.x * fq.x, fp.x, ax);
            ay = fmaf(v.y * fq.y, fp.y, ay);
            az = fmaf(v.z * fq.z, fp.z, az);
            aw = fmaf(v.w * fq.w, fp.w, aw);
        }
    }
    #pragma unroll
    for (int s = 16; s > 0; s >>= 1) {
        ax += __shfl_xor_sync(0xffffffff, ax, s);
        ay += __shfl_xor_sync(0xffffffff, ay, s);
        az += __shfl_xor_sync(0xffffffff, az, s);
        aw += __shfl_xor_sync(0xffffffff, aw, s);
    }
    if (lane == 0) { wacc[warp][0] = ax; wacc[warp][1] = ay; wacc[warp][2] = az; wacc[warp][3] = aw; }
    __syncthreads();
    if (tid < 4) {
        float s = 0.f;
        #pragma unroll
        for (int w = 0; w < 8; w++) s += wacc[w][tid];
        a2p_s[(n * 8 + chunk) * 4 + tid] = s;
    }
}

// ============================================================
// K7: gate = swish(a2 @ Wg^T + bg); fold into per-n 4x4 M.
// ============================================================
__global__ void k_gate(const float* __restrict__ Wg, const float* __restrict__ bg,
                       const float* __restrict__ Wt) {
    int n = threadIdx.x;
    if (n >= BN) return;
    float a2[4] = {0.f, 0.f, 0.f, 0.f};
    #pragma unroll
    for (int ch = 0; ch < 8; ch++)
        #pragma unroll
        for (int c = 0; c < 4; c++)
            a2[c] += a2p_s[(n * 8 + ch) * 4 + c];
    #pragma unroll
    for (int d = 0; d < 4; d++) {
        float pre = bg[d];
        #pragma unroll
        for (int c = 0; c < 4; c++) pre = fmaf(a2[c], Wg[d * 4 + c], pre);
        float gate = pre / (1.f + expf(-pre));
        #pragma unroll
        for (int c = 0; c < 4; c++) M_s[n * 16 + d * 4 + c] = gate * Wt[d * 4 + c];
    }
}

// ============================================================
// K8: x2d_new[n,p,q,:] = M[n] * x2d[n,p,q,:]  (pure stream, 512 MB r+w)
// ============================================================
__global__ void k_pass2(const float* __restrict__ x2d, float* __restrict__ x2dout) {
    int n = blockIdx.y;
    int tid = threadIdx.x;
    float m[16];
    #pragma unroll
    for (int i = 0; i < 16; i++) m[i] = M_s[n * 16 + i];
    const float4* in4  = (const float4*)x2d    + (size_t)n * 262144;
    float4*       out4 = (float4*)      x2dout + (size_t)n * 262144;
    int base = blockIdx.x * 4096 + tid;
    #pragma unroll 8
    for (int j = 0; j < 16; j++) {
        int idx = base + j * 256;
        float4 v = in4[idx];
        float4 o;
        o.x = m[0]  * v.x + m[1]  * v.y + m[2]  * v.z + m[3]  * v.w;
        o.y = m[4]  * v.x + m[5]  * v.y + m[6]  * v.z + m[7]  * v.w;
        o.z = m[8]  * v.x + m[9]  * v.y + m[10] * v.z + m[11] * v.w;
        o.w = m[12] * v.x + m[13] * v.y + m[14] * v.z + m[15] * v.w;
        out4[idx] = o;
    }
}

// ============================================================
extern "C" void kernel_launch(void* const* d_in, const int* in_sizes, int n_in,
                              void* d_out, int out_size) {
    const float* x1d = (const float*)d_in[0];
    const float* x2d = (const float*)d_in[1];
    const float* W1  = (const float*)d_in[2];
    const float* b1  = (const float*)d_in[3];
    const float* W2  = (const float*)d_in[4];
    const float* b2  = (const float*)d_in[5];
    const float* Wie = (const float*)d_in[6];
    const float* Wt  = (const float*)d_in[7];
    const float* Wg  = (const float*)d_in[8];
    const float* bg  = (const float*)d_in[9];
    float* out = (float*)d_out;
    float* x1dnew = out;                       // [64, 2048]
    float* x2dnew = out + (size_t)BN * REP;    // [64, 512, 512, 4]

    k_norm_gauge<<<BN, 256>>>(x1d);
    k_bn<<<4, 128>>>();
    k_gemm<<<dim3(64, 8), 256>>>(W1, b1, 0);   // swish
    k_gemm<<<dim3(64, 8), 256>>>(W2, b2, 1);   // linear
    k_ielin<<<dim3(128, 16), 256>>>(Wie, x1dnew);
    k_reduce<<<dim3(8, BN), 256>>>(x2d, x1dnew);
    k_gate<<<1, 64>>>(Wg, bg, Wt);
    k_pass2<<<dim3(64, BN), 256>>>(x2d, x2dnew);
}